// round 4
// baseline (speedup 1.0000x reference)
#include <cuda_runtime.h>
#include <math.h>

#define MM 48
#define LL 48
#define NN 256
#define NPAIR 1176        // 48*49/2 (m<=k)
#define NSLOT 1280        // 64 lanes * 20 slots (19 real + 1 pad)
#define SUFV4 320         // NSLOT/4 : float4 row stride
#define ZT 64             // zipper threads per sample
#define ZPJ 19            // pairs per zipper thread

// Scratch (static __device__ — allocation-free per harness rules)
__device__ float2 g_ab[(size_t)NN * LL * MM];       // (a,b) per (n,l,m)  ~4.7 MB
__device__ float  g_suf[(size_t)NN * LL * NSLOT];   // suffix products    ~62.9 MB

// Accurate f32 sincos: Cody-Waite FMA range reduction + Taylor polys.
// |x| < ~80, ~1-2 ulp, immune to --use_fast_math (no libm).
__device__ __forceinline__ void sincos_acc(float x, float* s, float* c) {
    float kf = rintf(x * 0.63661977236758134f);           // x * 2/pi
    int k = (int)kf;
    float r = fmaf(kf, -1.57079637050628662109375f, x);   // - k * fl32(pi/2)
    r = fmaf(kf, 4.37113882867379290e-8f, r);             // - k * lo correction
    float r2 = r * r;
    float ps = fmaf(r2, 2.7557314297e-06f, -1.9841270114e-04f);
    ps = fmaf(r2, ps, 8.3333337680e-03f);
    ps = fmaf(r2, ps, -1.6666667163e-01f);
    float sr = fmaf(r * r2, ps, r);
    float pc = fmaf(r2, -2.7557314297e-07f, 2.4760126951e-05f);
    pc = fmaf(r2, pc, -1.3888889225e-03f);
    pc = fmaf(r2, pc, 4.1666667908e-02f);
    float cr = fmaf(r2 * r2, pc, fmaf(r2, -0.5f, 1.0f));
    switch (k & 3) {
        case 0: *s = sr;  *c = cr;  break;
        case 1: *s = cr;  *c = -sr; break;
        case 2: *s = -sr; *c = -cr; break;
        default:*s = -cr; *c = sr;  break;
    }
}

// Kernel 1 (emb + theta + suffix): per-sample CTA computes the a/b tile
// (theta trig recomputed in-CTA — kills the separate theta launch), writes
// the tile for the zipper, then reverse-scans suffix products of full-site
// pair dots into the zipper's lane-chunked (64 x 20) layout.
__global__ __launch_bounds__(256) void suffix_kernel(
    const float* __restrict__ inp, const float* __restrict__ theta,
    const float* __restrict__ coef) {
    __shared__ float2 ab[LL * MM];
    __shared__ float inp_sh[LL];
    const int n = blockIdx.x, tid = threadIdx.x;

    if (tid < LL) inp_sh[tid] = inp[n * LL + tid];
    __syncthreads();

    float2* abg = g_ab + (size_t)n * (LL * MM);
    const float PI2F = 1.57079637050628662109375f;   // fl32(pi/2)
#pragma unroll
    for (int e = tid; e < LL * MM; e += 256) {
        int l = e / MM, m = e % MM;
        float ang = inp_sh[l] * ((float)(m + 1) * PI2F);   // f32 like ref
        float sa, ca; sincos_acc(ang, &sa, &ca);
        float st, ct; sincos_acc(theta[e], &st, &ct);
        float cf = coef[m];
        float2 v = make_float2(cf * (ct * ca - st * sa),   // a (p=0)
                               cf * (st * ca + ct * sa));  // b (p=1)
        ab[e] = v;
        abg[e] = v;
    }
    __syncthreads();

    // slot s = tid + 256*j : zipper-lane lz = s/20 owns pair 19*lz + (s%20)
    int pm[5], pk[5];
    float run[5];
#pragma unroll
    for (int j = 0; j < 5; j++) {
        int s = tid + 256 * j;
        int lz = s / 20, jj = s - lz * 20;
        int p = 19 * lz + jj;
        if (jj < 19 && p < NPAIR) {
            int m = 0, off = 0;
            while (off + (MM - m) <= p) { off += MM - m; m++; }
            pm[j] = m; pk[j] = m + (p - off);
            run[j] = (pm[j] == pk[j]) ? 1.0f : 2.0f;       // symmetry weight
        } else { pm[j] = 0; pk[j] = 0; run[j] = 0.0f; }    // pad -> 0
    }
    float* sufn = g_suf + (size_t)n * (LL * NSLOT);
    for (int l = LL - 1; l >= 0; l--) {
#pragma unroll
        for (int j = 0; j < 5; j++) {
            sufn[l * NSLOT + tid + 256 * j] = run[j];      // SUF excludes site l
            float2 vm = ab[l * MM + pm[j]];
            float2 vk = ab[l * MM + pk[j]];
            run[j] *= fmaf(vm.x, vk.x, vm.y * vk.y);
        }
    }
}

// Kernel 2: zipper with REGISTER-RESIDENT per-pair prefix products P_{mk}.
// No per-step g broadcast: P update is purely lane-local. 64 threads/sample,
// one butterfly + one barrier per step, redundant decisions on all threads.
__global__ __launch_bounds__(ZT) void zipper_kernel(
    const float* __restrict__ rand_u,   // (L,N)
    float* __restrict__ out)            // N*L bits then N probs
{
    __shared__ float2 ab[LL * MM];      // static a/b tile (18.4 KB)
    __shared__ float u_sh[LL];
    __shared__ float red[2][2][2];      // [parity][sum][warp]

    const int n = blockIdx.x, tid = threadIdx.x;
    const int lane = tid & 31, wid = tid >> 5;

    const float2* abg = g_ab + (size_t)n * (LL * MM);
#pragma unroll
    for (int e = tid; e < LL * MM; e += ZT) ab[e] = abg[e];
    if (tid < LL) u_sh[tid] = rand_u[tid * NN + n];

    // decode this lane's 19 contiguous pairs -> smem float2 offsets
    int offm[ZPJ], offk[ZPJ];
    float P[ZPJ];
    {
        int p0 = tid * ZPJ;
        int p0c = p0 < NPAIR ? p0 : NPAIR - 1;   // clamp (lanes 62,63 all-pad)
        int m = 0, off = 0;
        while (off + (MM - m) <= p0c) { off += MM - m; m++; }
        int k = m + (p0c - off);
#pragma unroll
        for (int j = 0; j < ZPJ; j++) {
            offm[j] = m; offk[j] = k;
            P[j] = (p0 + j < NPAIR) ? 1.0f : 0.0f;   // pads contribute exact 0
            if (++k == MM) { ++m; k = m; }
            if (m >= MM) { m = MM - 1; k = MM - 1; }
        }
    }

    const float4* sufv = reinterpret_cast<const float4*>(g_suf + (size_t)n * (LL * NSLOT));
    float4 sufA[5], sufB[5];
#pragma unroll
    for (int j = 0; j < 5; j++) sufA[j] = sufv[tid * 5 + j];   // row l=0

    float denom0 = 1.0f;
    int Kexp = 0;
    unsigned long long bits = 0ull;
    __syncthreads();

    for (int l = 0; l < LL; l++) {
        const float4* cu = (l & 1) ? sufB : sufA;
        float4* nx = (l & 1) ? sufA : sufB;
        // prefetch next site's suf row (L2 latency off the chain)
        if (l + 1 < LL) {
#pragma unroll
            for (int j = 0; j < 5; j++)
                nx[j] = sufv[(size_t)(l + 1) * SUFV4 + tid * 5 + j];
        }
        const float2* abl = ab + l * MM;
        float un = u_sh[l];

        float s0 = 0.0f, s1 = 0.0f;
        float aa[ZPJ], bb[ZPJ];
#pragma unroll
        for (int j = 0; j < ZPJ; j++) {
            float sf = ((j & 3) == 0) ? cu[j >> 2].x : ((j & 3) == 1) ? cu[j >> 2].y
                     : ((j & 3) == 2) ? cu[j >> 2].z : cu[j >> 2].w;
            float2 vm = abl[offm[j]], vk = abl[offk[j]];
            aa[j] = vm.x * vk.x;
            bb[j] = vm.y * vk.y;
            float ps = P[j] * sf;
            s0 = fmaf(ps, aa[j], s0);
            s1 = fmaf(ps, bb[j], s1);
        }
#pragma unroll
        for (int o = 16; o; o >>= 1) {
            s0 += __shfl_xor_sync(0xffffffffu, s0, o);
            s1 += __shfl_xor_sync(0xffffffffu, s1, o);
        }
        if (lane == 0) { red[l & 1][0][wid] = s0; red[l & 1][1][wid] = s1; }
        __syncthreads();

        float S0 = red[l & 1][0][0] + red[l & 1][0][1];
        float S1 = red[l & 1][1][0] + red[l & 1][1][1];
        float den = fabsf(S0 + S1);              // inner of prefix-masked MPS
        float p1  = fabsf(S1) / den;
        int bit = (un < p1) ? 1 : 0;
        if (l == 0) denom0 = den;
        int eb = (__float_as_int(den) >> 23) & 0xFF;   // exact 2^-k renorm
        int kk = eb ? (eb - 127) >> 1 : 0;
        Kexp += kk;
        float scale = __int_as_float((127 - kk) << 23);
        bits |= (unsigned long long)bit << l;
#pragma unroll
        for (int j = 0; j < ZPJ; j++)
            P[j] *= (bit ? bb[j] : aa[j]) * scale;       // lane-local update
    }

    // final inner = sum over pairs of w * P (w=2 for m<k, 1 for m==k; pads P=0)
    float sf = 0.0f;
#pragma unroll
    for (int j = 0; j < ZPJ; j++)
        sf += ((offm[j] == offk[j]) ? 1.0f : 2.0f) * P[j];
#pragma unroll
    for (int o = 16; o; o >>= 1) sf += __shfl_xor_sync(0xffffffffu, sf, o);
    __syncthreads();
    if (lane == 0) red[0][0][wid] = sf;
    __syncthreads();

    // outputs (bits identical across all 64 threads)
    if (tid < LL) out[n * LL + tid] = (float)((bits >> tid) & 1ull);
    if (tid == 0) {
        double Sf = (double)(red[0][0][0] + red[0][0][1]);  // inner_final * 2^-Kexp
        double pmv = ldexp(fabs(Sf), Kexp) / (double)denom0;
        out[NN * LL + n] = (float)pmv;
    }
}

extern "C" void kernel_launch(void* const* d_in, const int* in_sizes, int n_in,
                              void* d_out, int out_size) {
    const float* inp    = (const float*)d_in[0];   // (N,L)
    const float* theta  = (const float*)d_in[1];   // (L,M)
    const float* coef   = (const float*)d_in[2];   // (M,)
    const float* rand_u = (const float*)d_in[3];   // (L,N)
    float* out = (float*)d_out;

    suffix_kernel<<<NN, 256>>>(inp, theta, coef);
    zipper_kernel<<<NN, ZT>>>(rand_u, out);
}